// round 14
// baseline (speedup 1.0000x reference)
#include <cuda_runtime.h>

// ApsUp: polyphase 2x upsample + circular pad + depthwise 3x3 binomial blur,
// collapsed to a direct gather (only one of 4 phases is nonzero per batch).
//
// Shapes (fixed): inp [16,256,64,64] f32, poly [16] i32, out [16,256,128,128] f32.
//
// CONVERGED FORM (13 rounds of evidence):
//  - Wall: 268 MB compulsory output writes through HBM at ~5.4 TB/s effective
//    (~68% of spec — canonical write-stream efficiency). Direction-independent
//    (a read-and-skip-write variant timed identically).
//  - Structure-insensitive: 7 distinct structures all pin kernel time ~51us.
//  - Launch-shape optimum: 128-thread blocks x 65536 (finest last-wave quanta
//    without tripping the 32-CTA/SM slot limit; 64-thr blocks -> 32% occ, 72us).
//  - __stcs evict-first stores keep L2 for the resident 67 MB input.
//  - Run-to-run noise band: +/-0.3us (53.34 vs 53.66 on identical config).
//
// Structure: one warp per (channel, input-row-pair A); lane L owns output
// cols 4L..4L+3 of output rows 2A and 2A+1. Lane loads float2 (cols 2L,2L+1)
// from input rows A and a1 (= A+/-1 circular), vertical-combines in registers,
// horizontal circular neighbor via one warp shuffle per output row
// (32 lanes x 2 cols = 64 = N, so wrap == (lane +/- 1) & 31).

#define B_ 16
#define C_ 256
#define N_ 64
#define TWO_N 128

__global__ __launch_bounds__(128) void aps_up_kernel(
    const float* __restrict__ inp,
    const int*   __restrict__ poly,
    float*       __restrict__ out)
{
    // blockIdx.x = bc*16 + g ; warp w handles row pair A = g*4 + w
    const int bc = blockIdx.x >> 4;
    const int g  = blockIdx.x & 15;
    const int w  = threadIdx.x >> 5;
    const int L  = threadIdx.x & 31;
    const int A  = g * 4 + w;
    const int bb = bc >> 8;

    const int p = __ldg(&poly[bb]);
    const int r = p & 1;                  // row phase offset (warp-uniform)
    const int c = p >> 1;                 // col phase offset (warp-uniform)

    const int a1 = (A + (r ? (N_ - 1) : 1)) & (N_ - 1);

    const float* base = inp + (size_t)bc * (N_ * N_);
    const float2 f0 = *reinterpret_cast<const float2*>(base + A  * N_ + 2 * L);
    const float2 f1 = *reinterpret_cast<const float2*>(base + a1 * N_ + 2 * L);

    // Vertical combine (weights folded in):
    //   ve -> output row 2A + r      (weight 0.5 on row A)
    //   vo -> output row 2A + 1 - r  (weight 0.25 on rows A and a1)
    float2 ve, vo;
    ve.x = 0.5f * f0.x;
    ve.y = 0.5f * f0.y;
    vo.x = 0.25f * (f0.x + f1.x);
    vo.y = 0.25f * (f0.y + f1.y);

    // One shuffle pair serves both phases (warp-uniform select):
    //   c==0: need lane (L+1)'s v.x ; c==1: need lane (L-1)'s v.y
    const unsigned m   = 0xFFFFFFFFu;
    const int      src = (L + (c ? 31 : 1)) & 31;
    const float    veN = __shfl_sync(m, c ? ve.y : ve.x, src);
    const float    voN = __shfl_sync(m, c ? vo.y : vo.x, src);

    float* obase = out + (size_t)bc * (TWO_N * TWO_N) + 4 * L;
    float* rowE  = obase + (size_t)(2 * A + r)     * TWO_N;
    float* rowO  = obase + (size_t)(2 * A + 1 - r) * TWO_N;

    float4 oe, oo;
    if (c == 0) {
        oe.x = 0.5f  *  ve.x;
        oe.y = 0.25f * (ve.x + ve.y);
        oe.z = 0.5f  *  ve.y;
        oe.w = 0.25f * (ve.y + veN);
        oo.x = 0.5f  *  vo.x;
        oo.y = 0.25f * (vo.x + vo.y);
        oo.z = 0.5f  *  vo.y;
        oo.w = 0.25f * (vo.y + voN);
    } else {
        oe.x = 0.25f * (veN + ve.x);
        oe.y = 0.5f  *  ve.x;
        oe.z = 0.25f * (ve.x + ve.y);
        oe.w = 0.5f  *  ve.y;
        oo.x = 0.25f * (voN + vo.x);
        oo.y = 0.5f  *  vo.x;
        oo.z = 0.25f * (vo.x + vo.y);
        oo.w = 0.5f  *  vo.y;
    }
    __stcs(reinterpret_cast<float4*>(rowE), oe);
    __stcs(reinterpret_cast<float4*>(rowO), oo);
}

extern "C" void kernel_launch(void* const* d_in, const int* in_sizes, int n_in,
                              void* d_out, int out_size)
{
    const float* inp  = (const float*)d_in[0];
    const int*   poly = (const int*)d_in[1];
    float*       out  = (float*)d_out;

    // 4096 channels * 16 blocks each (4 warps/block, 1 warp per row pair)
    aps_up_kernel<<<B_ * C_ * 16, 128>>>(inp, poly, out);
}

// round 15
// speedup vs baseline: 1.0030x; 1.0030x over previous
#include <cuda_runtime.h>

// ApsUp: polyphase 2x upsample + circular pad + depthwise 3x3 binomial blur,
// collapsed to a direct gather (only one of 4 phases is nonzero per batch).
//
// Shapes (fixed): inp [16,256,64,64] f32, poly [16] i32, out [16,256,128,128] f32.
//
// FINAL CONVERGED FORM (14 rounds):
//  - Wall: 268 MB compulsory output writes at ~5.45 TB/s effective (~68% of
//    8 TB/s spec = canonical HBM write-stream ceiling). Direction-independent:
//    a read-and-skip-write variant timed identically (R10).
//  - Structure-insensitive: 7 distinct structures all pin kernel ~51us.
//  - Launch-shape optimum: 128-thread blocks x 65536 blocks (finest last-wave
//    quanta without occupancy collapse; 64-thr blocks -> 32% occ, 72us;
//    block-per-channel -> +3us straggler tail).
//  - __stcs evict-first stores keep L2 for the resident 67 MB input.
//  - Noise band +/-0.3us verified over 3 identical-config runs.
//
// Structure: one warp per (channel, input-row-pair A); lane L owns output
// cols 4L..4L+3 of output rows 2A and 2A+1. Lane loads float2 (cols 2L,2L+1)
// from input rows A and a1 (= A+/-1 circular), vertical-combines in registers,
// horizontal circular neighbor via one warp-shuffle pair (32 lanes x 2 cols
// = 64 = N, so the circular wrap is exactly (lane +/- 1) & 31).

#define B_ 16
#define C_ 256
#define N_ 64
#define TWO_N 128

__global__ __launch_bounds__(128) void aps_up_kernel(
    const float* __restrict__ inp,
    const int*   __restrict__ poly,
    float*       __restrict__ out)
{
    // blockIdx.x = bc*16 + g ; warp w handles row pair A = g*4 + w
    const int bc = blockIdx.x >> 4;
    const int g  = blockIdx.x & 15;
    const int w  = threadIdx.x >> 5;
    const int L  = threadIdx.x & 31;
    const int A  = g * 4 + w;
    const int bb = bc >> 8;

    const int p = __ldg(&poly[bb]);
    const int r = p & 1;                  // row phase offset (warp-uniform)
    const int c = p >> 1;                 // col phase offset (warp-uniform)

    const int a1 = (A + (r ? (N_ - 1) : 1)) & (N_ - 1);

    const float* base = inp + (size_t)bc * (N_ * N_);
    const float2 f0 = *reinterpret_cast<const float2*>(base + A  * N_ + 2 * L);
    const float2 f1 = *reinterpret_cast<const float2*>(base + a1 * N_ + 2 * L);

    // Vertical combine (weights folded in):
    //   ve -> output row 2A + r      (weight 0.5 on row A)
    //   vo -> output row 2A + 1 - r  (weight 0.25 on rows A and a1)
    float2 ve, vo;
    ve.x = 0.5f * f0.x;
    ve.y = 0.5f * f0.y;
    vo.x = 0.25f * (f0.x + f1.x);
    vo.y = 0.25f * (f0.y + f1.y);

    // One shuffle pair serves both phases (warp-uniform select):
    //   c==0: need lane (L+1)'s v.x ; c==1: need lane (L-1)'s v.y
    const unsigned m   = 0xFFFFFFFFu;
    const int      src = (L + (c ? 31 : 1)) & 31;
    const float    veN = __shfl_sync(m, c ? ve.y : ve.x, src);
    const float    voN = __shfl_sync(m, c ? vo.y : vo.x, src);

    float* obase = out + (size_t)bc * (TWO_N * TWO_N) + 4 * L;
    float* rowE  = obase + (size_t)(2 * A + r)     * TWO_N;
    float* rowO  = obase + (size_t)(2 * A + 1 - r) * TWO_N;

    float4 oe, oo;
    if (c == 0) {
        oe.x = 0.5f  *  ve.x;
        oe.y = 0.25f * (ve.x + ve.y);
        oe.z = 0.5f  *  ve.y;
        oe.w = 0.25f * (ve.y + veN);
        oo.x = 0.5f  *  vo.x;
        oo.y = 0.25f * (vo.x + vo.y);
        oo.z = 0.5f  *  vo.y;
        oo.w = 0.25f * (vo.y + voN);
    } else {
        oe.x = 0.25f * (veN + ve.x);
        oe.y = 0.5f  *  ve.x;
        oe.z = 0.25f * (ve.x + ve.y);
        oe.w = 0.5f  *  ve.y;
        oo.x = 0.25f * (voN + vo.x);
        oo.y = 0.5f  *  vo.x;
        oo.z = 0.25f * (vo.x + vo.y);
        oo.w = 0.5f  *  vo.y;
    }
    __stcs(reinterpret_cast<float4*>(rowE), oe);
    __stcs(reinterpret_cast<float4*>(rowO), oo);
}

extern "C" void kernel_launch(void* const* d_in, const int* in_sizes, int n_in,
                              void* d_out, int out_size)
{
    const float* inp  = (const float*)d_in[0];
    const int*   poly = (const int*)d_in[1];
    float*       out  = (float*)d_out;

    // 4096 channels * 16 blocks each (4 warps/block, 1 warp per row pair)
    aps_up_kernel<<<B_ * C_ * 16, 128>>>(inp, poly, out);
}